// round 1
// baseline (speedup 1.0000x reference)
#include <cuda_runtime.h>

#define L 36864
#define HH 192
#define NHASH 4
#define TOT (NHASH*L)        // 147456
#define CHUNK_ 144
#define NCHUNK 256
#define NCODES 512
#define TILE 1024
#define NTILES 144           // TOT / TILE

// ---------------- scratch (device globals; no allocations allowed) ----------
__device__ __align__(16) float g_xe[L*8];        // x_embed  [L][8]
__device__ __align__(16) float g_ye[L*32];       // y_embed  [L][32]
__device__ int   g_code[TOT];                    // hash codes (with h*128 offset)
__device__ int   g_tileHist[NTILES*NCODES];
__device__ int   g_tileOff[NTILES*NCODES];
__device__ int   g_sortIdx[TOT];                 // sorted pos -> original p
__device__ int   g_undo[TOT];                    // original p -> sorted pos
__device__ __align__(16) float g_xq[TOT*8];      // sorted queries (unnormalized)
__device__ __align__(16) float g_xn[TOT*8];      // sorted keys (normalized)
__device__ __align__(16) float g_ys[TOT*32];     // sorted values
__device__ __align__(16) float g_ret[TOT*32];    // attention output (sorted order)
__device__ float g_bs[TOT];                      // bucket scores (sorted order)

// ---------------- K1: fused convs + LSH hashing -----------------------------
__global__ void k_embed_hash(const float* __restrict__ x,
                             const float* __restrict__ wm,
                             const float* __restrict__ bm,
                             const float* __restrict__ wa,
                             const float* __restrict__ ba,
                             const float* __restrict__ rot) {
    __shared__ float s_wm[2304];                 // [co=8][ci=32][3][3]
    __shared__ float s_wa[1024];                 // [co=32][ci=32]
    __shared__ __align__(16) float s_rot[2048];  // transposed: [(h*64+i)][f=8]
    __shared__ float s_bm[8];
    __shared__ float s_ba[32];
    int tid = threadIdx.x;
    for (int t = tid; t < 2304; t += 128) s_wm[t] = wm[t];
    for (int t = tid; t < 1024; t += 128) s_wa[t] = wa[t];
    for (int t = tid; t < 2048; t += 128) {
        int f = t >> 8; int rem = t & 255;       // rem = h*64 + i
        s_rot[rem*8 + f] = rot[t];               // rot layout [f][h][i]
    }
    if (tid < 8)  s_bm[tid] = bm[tid];
    if (tid < 32) s_ba[tid] = ba[tid];
    __syncthreads();

    int pix = blockIdx.x*128 + tid;              // 288*128 == L exactly
    int py = pix / HH, px = pix - py*HH;
    float am[8], aa[32];
#pragma unroll
    for (int c = 0; c < 8;  c++) am[c] = s_bm[c];
#pragma unroll
    for (int c = 0; c < 32; c++) aa[c] = s_ba[c];

    bool yl = py > 0, yh = py < HH-1, xl = px > 0, xh = px < HH-1;
    for (int ci = 0; ci < 32; ci++) {
        const float* xc = x + ci*L + py*HH + px;
        float v[9];
        v[4] = xc[0];
        v[0] = (yl&&xl) ? xc[-HH-1] : 0.f;
        v[1] = yl        ? xc[-HH]   : 0.f;
        v[2] = (yl&&xh) ? xc[-HH+1] : 0.f;
        v[3] = xl        ? xc[-1]    : 0.f;
        v[5] = xh        ? xc[1]     : 0.f;
        v[6] = (yh&&xl) ? xc[HH-1]  : 0.f;
        v[7] = yh        ? xc[HH]    : 0.f;
        v[8] = (yh&&xh) ? xc[HH+1]  : 0.f;
#pragma unroll
        for (int co = 0; co < 8; co++) {
            const float* w = &s_wm[(co*32+ci)*9];
#pragma unroll
            for (int t = 0; t < 9; t++) am[co] += w[t]*v[t];
        }
        float vc = v[4];
#pragma unroll
        for (int co = 0; co < 32; co++) aa[co] += s_wa[co*32+ci]*vc;
    }
#pragma unroll
    for (int c = 0; c < 8;  c++) g_xe[pix*8+c]  = am[c];
#pragma unroll
    for (int c = 0; c < 32; c++) g_ye[pix*32+c] = aa[c];

    // 4 LSH hashes: argmax over concat([r, -r]) of 64 rotated dims
    const float4* r4 = (const float4*)s_rot;
    float4 e0 = make_float4(am[0],am[1],am[2],am[3]);
    float4 e1 = make_float4(am[4],am[5],am[6],am[7]);
    for (int h = 0; h < NHASH; h++) {
        float bP = -1e30f, bN = -1e30f; int iP = 0, iN = 0;
        for (int i = 0; i < 64; i++) {
            float4 a = r4[(h*64+i)*2];
            float4 b = r4[(h*64+i)*2+1];
            float r = e0.x*a.x + e0.y*a.y + e0.z*a.z + e0.w*a.w
                    + e1.x*b.x + e1.y*b.y + e1.z*b.z + e1.w*b.w;
            if ( r > bP) { bP =  r; iP = i; }
            if (-r > bN) { bN = -r; iN = i; }
        }
        // first-occurrence argmax: +r block (idx 0..63) wins ties vs -r block
        int code = (bN > bP) ? (64 + iN) : iP;
        g_code[h*L + pix] = code + h*128;
    }
}

// ---------------- stable counting sort (512 bins) ---------------------------
__global__ void k_hist() {
    __shared__ int hsh[NCODES];
    int tile = blockIdx.x;
    for (int c = threadIdx.x; c < NCODES; c += 256) hsh[c] = 0;
    __syncthreads();
    for (int t = threadIdx.x; t < TILE; t += 256)
        atomicAdd(&hsh[g_code[tile*TILE + t]], 1);
    __syncthreads();
    for (int c = threadIdx.x; c < NCODES; c += 256)
        g_tileHist[tile*NCODES + c] = hsh[c];
}

__global__ void k_scan() {                       // 1 block, 512 threads
    __shared__ int s_tot[NCODES];
    int c = threadIdx.x;
    int run = 0;
    for (int t = 0; t < NTILES; t++) {
        g_tileOff[t*NCODES + c] = run;
        run += g_tileHist[t*NCODES + c];
    }
    s_tot[c] = run;
    __syncthreads();
    // Hillis-Steele inclusive scan over 512 entries
    for (int off = 1; off < NCODES; off <<= 1) {
        int v = s_tot[c];
        int add = (c >= off) ? s_tot[c - off] : 0;
        __syncthreads();
        s_tot[c] = v + add;
        __syncthreads();
    }
    int start = (c == 0) ? 0 : s_tot[c-1];       // exclusive prefix
    for (int t = 0; t < NTILES; t++) g_tileOff[t*NCODES + c] += start;
}

__global__ void k_scatter() {                    // 1 warp per tile, stable
    __shared__ int cnt[NCODES];
    int tile = blockIdx.x;
    int lane = threadIdx.x;
    for (int c = lane; c < NCODES; c += 32) cnt[c] = 0;
    __syncwarp();
    for (int r = 0; r < TILE/32; r++) {
        int p = tile*TILE + r*32 + lane;
        int c = g_code[p];
        unsigned mask = __match_any_sync(0xffffffffu, c);
        int leader = __ffs(mask) - 1;
        int below  = __popc(mask & ((1u << lane) - 1u));
        int base = 0;
        if (lane == leader) base = cnt[c];
        base = __shfl_sync(0xffffffffu, base, leader);
        int dest = g_tileOff[tile*NCODES + c] + base + below;
        g_sortIdx[dest] = p;
        g_undo[p] = dest;
        if (lane == leader) cnt[c] = base + __popc(mask);
        __syncwarp();
    }
}

// ---------------- gather sorted q / normalized k / v ------------------------
__global__ void k_gather() {                     // 1 warp per sorted row
    int gtid = blockIdx.x*blockDim.x + threadIdx.x;
    int s = gtid >> 5;
    int lane = threadIdx.x & 31;
    if (s >= TOT) return;
    int p = g_sortIdx[s];
    int l = p % L;
    float v = 0.f;
    if (lane < 8) v = g_xe[l*8 + lane];
    float sq = v*v;
    sq += __shfl_xor_sync(0xffffffffu, sq, 1);
    sq += __shfl_xor_sync(0xffffffffu, sq, 2);
    sq += __shfl_xor_sync(0xffffffffu, sq, 4);
    float nrm = sqrtf(sq);
    float inv = 1.f / fmaxf(nrm, 5e-5f);
    if (lane < 8) {
        g_xq[s*8 + lane] = v;
        g_xn[s*8 + lane] = v*inv;
    }
    g_ys[s*32 + lane] = g_ye[l*32 + lane];
}

// ---------------- chunked softmax attention ---------------------------------
__global__ __launch_bounds__(160) void k_attn() {
    __shared__ float4 s_xb[288];                 // 144 queries  x 8f
    __shared__ float4 s_xm[864];                 // 432 keys     x 8f
    __shared__ float4 s_y[384];                  // 48-row value tile x 32f
    int blk = blockIdx.x;
    int h = blk >> 8, k = blk & 255;
    int tid = threadIdx.x;
    int hb = h*L;
    int kb0 = k, kb1 = (k + NCHUNK - 1) & (NCHUNK-1), kb2 = (k + 1) & (NCHUNK-1);
    int baseQ = hb + k*CHUNK_;
    const float4* xq4 = (const float4*)g_xq;
    const float4* xn4 = (const float4*)g_xn;
    for (int t = tid; t < 288; t += 160) s_xb[t] = xq4[baseQ*2 + t];
    int sb0 = (hb + kb0*CHUNK_)*2, sb1 = (hb + kb1*CHUNK_)*2, sb2 = (hb + kb2*CHUNK_)*2;
    for (int t = tid; t < 864; t += 160) {
        int seg = t / 288; int r = t - seg*288;
        int sb = (seg == 0) ? sb0 : ((seg == 1) ? sb1 : sb2);
        s_xm[t] = xn4[sb + r];
    }
    __syncthreads();

    int i = tid;
    float4 q0, q1;
    float m = -1e30f;
    if (i < CHUNK_) {
        q0 = s_xb[2*i]; q1 = s_xb[2*i+1];
        for (int j = 0; j < 432; j++) {
            float4 a = s_xm[2*j], b = s_xm[2*j+1];
            float s = q0.x*a.x + q0.y*a.y + q0.z*a.z + q0.w*a.w
                    + q1.x*b.x + q1.y*b.y + q1.z*b.z + q1.w*b.w;
            m = fmaxf(m, s);
        }
    }
    float acc[32];
#pragma unroll
    for (int c = 0; c < 32; c++) acc[c] = 0.f;
    float lsum = 0.f;
    const float4* ys4 = (const float4*)g_ys;
    int yb0 = (hb + kb0*CHUNK_)*8, yb1 = (hb + kb1*CHUNK_)*8, yb2 = (hb + kb2*CHUNK_)*8;

    for (int jt = 0; jt < 432; jt += 48) {
        __syncthreads();
        for (int t = tid; t < 384; t += 160) {
            int jr = t >> 3, q = t & 7;
            int j = jt + jr;
            int seg = j / 144; int rr = j - seg*144;
            int yb = (seg == 0) ? yb0 : ((seg == 1) ? yb1 : yb2);
            s_y[t] = ys4[yb + rr*8 + q];
        }
        __syncthreads();
        if (i < CHUNK_) {
#pragma unroll 4
            for (int jj = 0; jj < 48; jj++) {
                int j = jt + jj;
                float4 a = s_xm[2*j], b = s_xm[2*j+1];
                float s = q0.x*a.x + q0.y*a.y + q0.z*a.z + q0.w*a.w
                        + q1.x*b.x + q1.y*b.y + q1.z*b.z + q1.w*b.w;
                float p = __expf(s - m);
                lsum += p;
                const float4* yr = &s_y[jj*8];
#pragma unroll
                for (int q = 0; q < 8; q++) {
                    float4 yv = yr[q];
                    acc[4*q+0] += p*yv.x;
                    acc[4*q+1] += p*yv.y;
                    acc[4*q+2] += p*yv.z;
                    acc[4*q+3] += p*yv.w;
                }
            }
        }
    }
    if (i < CHUNK_) {
        float inv = 1.f / lsum;
        int row = baseQ + i;
        float4* o = ((float4*)g_ret) + row*8;
#pragma unroll
        for (int q = 0; q < 8; q++)
            o[q] = make_float4(acc[4*q]*inv, acc[4*q+1]*inv, acc[4*q+2]*inv, acc[4*q+3]*inv);
        g_bs[row] = m + __logf(lsum);
    }
}

// ---------------- un-sort + cross-hash softmax + residual -------------------
__global__ void k_combine(const float* __restrict__ x, float* __restrict__ out) {
    __shared__ int   s_d[4][32];
    __shared__ float s_p[4][32];
    int tx = threadIdx.x, c = threadIdx.y;
    int l = blockIdx.x*32 + tx;
    if (c < 4) {
        int d = g_undo[c*L + l];
        s_d[c][tx] = d;
        s_p[c][tx] = g_bs[d];
    }
    __syncthreads();
    if (c == 0) {
        float b0 = s_p[0][tx], b1 = s_p[1][tx], b2 = s_p[2][tx], b3 = s_p[3][tx];
        float mm = fmaxf(fmaxf(b0,b1), fmaxf(b2,b3));
        float e0 = __expf(b0-mm), e1 = __expf(b1-mm), e2 = __expf(b2-mm), e3 = __expf(b3-mm);
        float inv = 1.f/(e0+e1+e2+e3);
        s_p[0][tx] = e0*inv; s_p[1][tx] = e1*inv; s_p[2][tx] = e2*inv; s_p[3][tx] = e3*inv;
    }
    __syncthreads();
    float sum = 0.f;
#pragma unroll
    for (int h = 0; h < 4; h++)
        sum += s_p[h][tx] * g_ret[s_d[h][tx]*32 + c];
    out[c*L + l] = sum + x[c*L + l];
}

// ---------------- launcher --------------------------------------------------
extern "C" void kernel_launch(void* const* d_in, const int* in_sizes, int n_in,
                              void* d_out, int out_size) {
    const float* x   = (const float*)d_in[0];
    const float* wm  = (const float*)d_in[1];
    const float* bm  = (const float*)d_in[2];
    const float* wa  = (const float*)d_in[3];
    const float* ba  = (const float*)d_in[4];
    const float* rot = (const float*)d_in[5];
    float* out = (float*)d_out;

    k_embed_hash<<<L/128, 128>>>(x, wm, bm, wa, ba, rot);
    k_hist<<<NTILES, 256>>>();
    k_scan<<<1, NCODES>>>();
    k_scatter<<<NTILES, 32>>>();
    k_gather<<<TOT/8, 256>>>();
    k_attn<<<NHASH*NCHUNK, 160>>>();
    k_combine<<<L/32, dim3(32,32)>>>(x, out);
}

// round 2
// speedup vs baseline: 1.9788x; 1.9788x over previous
#include <cuda_runtime.h>

#define L 36864
#define HH 192
#define NHASH 4
#define TOT (NHASH*L)        // 147456
#define CHUNK_ 144
#define NCHUNK 256
#define NCODES 512
#define TILE 1024
#define NTILES 144           // TOT / TILE

// ---------------- scratch ----------------------------------------------------
__device__ __align__(16) float g_xe[L*8];
__device__ __align__(16) float g_ye[L*32];
__device__ int   g_code[TOT];
__device__ int   g_tileHist[NCODES*NTILES];      // TRANSPOSED: [code][tile]
__device__ int   g_tileOff[NCODES*NTILES];       // per-code exclusive over tiles
__device__ int   g_codeTot[NCODES];
__device__ int   g_codeStart[NCODES];
__device__ int   g_sortIdx[TOT];
__device__ int   g_undo[TOT];
__device__ __align__(16) float g_xq[TOT*8];
__device__ __align__(16) float g_xn[TOT*8];
__device__ __align__(16) float g_ys[TOT*32];
__device__ __align__(16) float g_ret[TOT*32];
__device__ float g_bs[TOT];

// ---------------- f32x2 helpers ----------------------------------------------
__device__ __forceinline__ unsigned long long ffma2(unsigned long long a,
                                                    unsigned long long b,
                                                    unsigned long long c) {
    unsigned long long d;
    asm("fma.rn.f32x2 %0, %1, %2, %3;" : "=l"(d) : "l"(a), "l"(b), "l"(c));
    return d;
}
__device__ __forceinline__ unsigned long long fmul2(unsigned long long a,
                                                    unsigned long long b) {
    unsigned long long d;
    asm("mul.rn.f32x2 %0, %1, %2;" : "=l"(d) : "l"(a), "l"(b));
    return d;
}
__device__ __forceinline__ unsigned long long pack2(float lo, float hi) {
    unsigned long long d;
    asm("mov.b64 %0, {%1, %2};" : "=l"(d)
        : "r"(__float_as_uint(lo)), "r"(__float_as_uint(hi)));
    return d;
}
__device__ __forceinline__ void unpack2(unsigned long long v, float& lo, float& hi) {
    unsigned int a, b;
    asm("mov.b64 {%0, %1}, %2;" : "=r"(a), "=r"(b) : "l"(v));
    lo = __uint_as_float(a); hi = __uint_as_float(b);
}

// ---------------- K1: fused convs + LSH hashing ------------------------------
__global__ void k_embed_hash(const float* __restrict__ x,
                             const float* __restrict__ wm,
                             const float* __restrict__ bm,
                             const float* __restrict__ wa,
                             const float* __restrict__ ba,
                             const float* __restrict__ rot) {
    __shared__ float s_wm[2304];
    __shared__ float s_wa[1024];
    __shared__ __align__(16) float s_rot[2048];  // transposed: [(h*64+i)][f=8]
    __shared__ float s_bm[8];
    __shared__ float s_ba[32];
    int tid = threadIdx.x;
    for (int t = tid; t < 2304; t += 128) s_wm[t] = wm[t];
    for (int t = tid; t < 1024; t += 128) s_wa[t] = wa[t];
    for (int t = tid; t < 2048; t += 128) {
        int f = t >> 8; int rem = t & 255;
        s_rot[rem*8 + f] = rot[t];
    }
    if (tid < 8)  s_bm[tid] = bm[tid];
    if (tid < 32) s_ba[tid] = ba[tid];
    __syncthreads();

    int pix = blockIdx.x*128 + tid;
    int py = pix / HH, px = pix - py*HH;
    float am[8], aa[32];
#pragma unroll
    for (int c = 0; c < 8;  c++) am[c] = s_bm[c];
#pragma unroll
    for (int c = 0; c < 32; c++) aa[c] = s_ba[c];

    bool yl = py > 0, yh = py < HH-1, xl = px > 0, xh = px < HH-1;
    for (int ci = 0; ci < 32; ci++) {
        const float* xc = x + ci*L + py*HH + px;
        float v[9];
        v[4] = xc[0];
        v[0] = (yl&&xl) ? xc[-HH-1] : 0.f;
        v[1] = yl        ? xc[-HH]   : 0.f;
        v[2] = (yl&&xh) ? xc[-HH+1] : 0.f;
        v[3] = xl        ? xc[-1]    : 0.f;
        v[5] = xh        ? xc[1]     : 0.f;
        v[6] = (yh&&xl) ? xc[HH-1]  : 0.f;
        v[7] = yh        ? xc[HH]    : 0.f;
        v[8] = (yh&&xh) ? xc[HH+1]  : 0.f;
#pragma unroll
        for (int co = 0; co < 8; co++) {
            const float* w = &s_wm[(co*32+ci)*9];
#pragma unroll
            for (int t = 0; t < 9; t++) am[co] += w[t]*v[t];
        }
        float vc = v[4];
#pragma unroll
        for (int co = 0; co < 32; co++) aa[co] += s_wa[co*32+ci]*vc;
    }
#pragma unroll
    for (int c = 0; c < 8;  c++) g_xe[pix*8+c]  = am[c];
#pragma unroll
    for (int c = 0; c < 32; c++) g_ye[pix*32+c] = aa[c];

    const float4* r4 = (const float4*)s_rot;
    float4 e0 = make_float4(am[0],am[1],am[2],am[3]);
    float4 e1 = make_float4(am[4],am[5],am[6],am[7]);
    for (int h = 0; h < NHASH; h++) {
        float bP = -1e30f, bN = -1e30f; int iP = 0, iN = 0;
        for (int i = 0; i < 64; i++) {
            float4 a = r4[(h*64+i)*2];
            float4 b = r4[(h*64+i)*2+1];
            float r = e0.x*a.x + e0.y*a.y + e0.z*a.z + e0.w*a.w
                    + e1.x*b.x + e1.y*b.y + e1.z*b.z + e1.w*b.w;
            if ( r > bP) { bP =  r; iP = i; }
            if (-r > bN) { bN = -r; iN = i; }
        }
        int code = (bN > bP) ? (64 + iN) : iP;
        g_code[h*L + pix] = code + h*128;
    }
}

// ---------------- stable counting sort (512 bins) ----------------------------
__global__ void k_hist() {
    __shared__ int hsh[NCODES];
    int tile = blockIdx.x;
    for (int c = threadIdx.x; c < NCODES; c += 256) hsh[c] = 0;
    __syncthreads();
    for (int t = threadIdx.x; t < TILE; t += 256)
        atomicAdd(&hsh[g_code[tile*TILE + t]], 1);
    __syncthreads();
    for (int c = threadIdx.x; c < NCODES; c += 256)
        g_tileHist[c*NTILES + tile] = hsh[c];          // transposed
}

// one warp per code: prefix over 144 tiles
__global__ void k_scanA() {                            // 64 blocks x 256
    int c = blockIdx.x*8 + (threadIdx.x >> 5);
    int lane = threadIdx.x & 31;
    int run = 0;
    for (int base = 0; base < NTILES; base += 32) {
        int t = base + lane;
        int v = (t < NTILES) ? g_tileHist[c*NTILES + t] : 0;
        int incl = v;
#pragma unroll
        for (int o = 1; o < 32; o <<= 1) {
            int u = __shfl_up_sync(0xffffffffu, incl, o);
            if (lane >= o) incl += u;
        }
        if (t < NTILES) g_tileOff[c*NTILES + t] = run + incl - v;
        run += __shfl_sync(0xffffffffu, incl, 31);
    }
    if (lane == 0) g_codeTot[c] = run;
}

__global__ void k_scanB() {                            // 1 block, 512 threads
    __shared__ int s[NCODES];
    int c = threadIdx.x;
    s[c] = g_codeTot[c];
    __syncthreads();
    for (int off = 1; off < NCODES; off <<= 1) {
        int v = s[c];
        int add = (c >= off) ? s[c - off] : 0;
        __syncthreads();
        s[c] = v + add;
        __syncthreads();
    }
    g_codeStart[c] = (c == 0) ? 0 : s[c-1];
}

// 8 warps per tile, stable
__global__ void k_scatter() {
    __shared__ int wcnt[8*NCODES];
    int tile = blockIdx.x;
    int tid = threadIdx.x, w = tid >> 5, lane = tid & 31;
    for (int c = tid; c < 8*NCODES; c += 256) wcnt[c] = 0;
    __syncthreads();
    int codes[4];
#pragma unroll
    for (int r = 0; r < 4; r++) {
        int p = tile*TILE + w*128 + r*32 + lane;
        int c = codes[r] = g_code[p];
        unsigned mask = __match_any_sync(0xffffffffu, c);
        int leader = __ffs(mask) - 1;
        if (lane == leader) wcnt[w*NCODES + c] += __popc(mask);
        __syncwarp();
    }
    __syncthreads();
    for (int c = tid; c < NCODES; c += 256) {
        int run = g_codeStart[c] + g_tileOff[c*NTILES + tile];
#pragma unroll
        for (int ww = 0; ww < 8; ww++) {
            int v = wcnt[ww*NCODES + c];
            wcnt[ww*NCODES + c] = run;
            run += v;
        }
    }
    __syncthreads();
#pragma unroll
    for (int r = 0; r < 4; r++) {
        int p = tile*TILE + w*128 + r*32 + lane;
        int c = codes[r];
        unsigned mask = __match_any_sync(0xffffffffu, c);
        int leader = __ffs(mask) - 1;
        int below  = __popc(mask & ((1u << lane) - 1u));
        int base = 0;
        if (lane == leader) {
            base = wcnt[w*NCODES + c];
            wcnt[w*NCODES + c] = base + __popc(mask);
        }
        base = __shfl_sync(0xffffffffu, base, leader);
        int dest = base + below;
        g_sortIdx[dest] = p;
        g_undo[p] = dest;
        __syncwarp();
    }
}

// ---------------- gather: 8 threads per sorted row ---------------------------
__global__ void k_gather() {                           // TOT*8/256 blocks
    int gt = blockIdx.x*256 + threadIdx.x;
    int s = gt >> 3, q = gt & 7;
    int p = g_sortIdx[s];
    int l = p % L;
    float v = g_xe[l*8 + q];
    float sq = v*v;
    sq += __shfl_xor_sync(0xffffffffu, sq, 1);
    sq += __shfl_xor_sync(0xffffffffu, sq, 2);
    sq += __shfl_xor_sync(0xffffffffu, sq, 4);
    float inv = 1.f / fmaxf(sqrtf(sq), 5e-5f);
    g_xq[s*8 + q] = v;
    g_xn[s*8 + q] = v*inv;
    ((float4*)g_ys)[s*8 + q] = ((const float4*)g_ye)[l*8 + q];
}

// ---------------- chunked attention: online softmax + f32x2 ------------------
__global__ __launch_bounds__(160, 1) void k_attn() {
    __shared__ __align__(16) unsigned long long s_kp[216*8]; // packed key pairs
    __shared__ __align__(16) float4 s_buf[864];              // raw keys, then value tiles
    int blk = blockIdx.x;
    int h = blk >> 8, k = blk & 255;
    int tid = threadIdx.x;
    int hb = h*L;
    int kb1 = (k + 255) & 255, kb2 = (k + 1) & 255;
    int baseQ = hb + k*CHUNK_;
    int sb0 = hb + k*CHUNK_, sb1 = hb + kb1*CHUNK_, sb2 = hb + kb2*CHUNK_;
    const float4* xn4 = (const float4*)g_xn;
    for (int t = tid; t < 864; t += 160) {
        int seg = t / 288; int r = t - seg*288;
        int sb = (seg == 0) ? sb0 : ((seg == 1) ? sb1 : sb2);
        s_buf[t] = xn4[sb*2 + r];
    }
    __syncthreads();
    const float* f = (const float*)s_buf;
    for (int e = tid; e < 1728; e += 160) {
        int jp = e >> 3, d = e & 7;
        s_kp[e] = pack2(f[(jp*2)*8 + d], f[(jp*2+1)*8 + d]);
    }

    int i = tid;
    unsigned long long qq[8];
    unsigned long long acc[16];
    float m = -1e30f, lsum = 0.f;
    if (i < CHUNK_) {
        const float* qp = g_xq + (size_t)(baseQ + i)*8;
#pragma unroll
        for (int d = 0; d < 8; d++) { float qv = qp[d]; qq[d] = pack2(qv, qv); }
#pragma unroll
        for (int q = 0; q < 16; q++) acc[q] = 0ull;
    }
    int yb0 = sb0*8, yb1 = sb1*8, yb2 = sb2*8;
    const float4* ys4 = (const float4*)g_ys;

    for (int t = 0; t < 12; t++) {
        int seg = t >> 2; int rr0 = (t & 3)*36;
        int yb = (seg == 0) ? yb0 : ((seg == 1) ? yb1 : yb2);
        __syncthreads();
        for (int e = tid; e < 288; e += 160) {
            int jr = e >> 3, q = e & 7;
            s_buf[e] = ys4[yb + (rr0 + jr)*8 + q];
        }
        __syncthreads();
        if (i < CHUNK_) {
            float s[36]; float tm = -1e30f;
#pragma unroll
            for (int jp = 0; jp < 18; jp++) {
                const unsigned long long* kp = &s_kp[(t*18 + jp)*8];
                unsigned long long sp = 0ull;
#pragma unroll
                for (int d = 0; d < 8; d++) sp = ffma2(qq[d], kp[d], sp);
                float lo, hi; unpack2(sp, lo, hi);
                s[2*jp] = lo; s[2*jp+1] = hi;
                tm = fmaxf(tm, fmaxf(lo, hi));
            }
            float newM = fmaxf(m, tm);
            float sc = __expf(m - newM);
            m = newM; lsum *= sc;
            unsigned long long sc2 = pack2(sc, sc);
#pragma unroll
            for (int q = 0; q < 16; q++) acc[q] = fmul2(acc[q], sc2);
#pragma unroll
            for (int jj = 0; jj < 36; jj++) {
                float p = __expf(s[jj] - m);
                lsum += p;
                unsigned long long pp = pack2(p, p);
                const unsigned long long* yr = (const unsigned long long*)&s_buf[jj*8];
#pragma unroll
                for (int q = 0; q < 16; q++) acc[q] = ffma2(pp, yr[q], acc[q]);
            }
        }
    }
    if (i < CHUNK_) {
        float inv = 1.f / lsum;
        unsigned long long inv2 = pack2(inv, inv);
        int row = baseQ + i;
        unsigned long long* o = ((unsigned long long*)g_ret) + (size_t)row*16;
#pragma unroll
        for (int q = 0; q < 16; q++) o[q] = fmul2(acc[q], inv2);
        g_bs[row] = m + __logf(lsum);
    }
}

// ---------------- un-sort + cross-hash softmax + residual --------------------
__global__ void k_combine(const float* __restrict__ x, float* __restrict__ out) {
    __shared__ int   s_d[4][32];
    __shared__ float s_p[4][32];
    int tx = threadIdx.x, c = threadIdx.y;
    int l = blockIdx.x*32 + tx;
    if (c < 4) {
        int d = g_undo[c*L + l];
        s_d[c][tx] = d;
        s_p[c][tx] = g_bs[d];
    }
    __syncthreads();
    if (c == 0) {
        float b0 = s_p[0][tx], b1 = s_p[1][tx], b2 = s_p[2][tx], b3 = s_p[3][tx];
        float mm = fmaxf(fmaxf(b0,b1), fmaxf(b2,b3));
        float e0 = __expf(b0-mm), e1 = __expf(b1-mm), e2 = __expf(b2-mm), e3 = __expf(b3-mm);
        float inv = 1.f/(e0+e1+e2+e3);
        s_p[0][tx] = e0*inv; s_p[1][tx] = e1*inv; s_p[2][tx] = e2*inv; s_p[3][tx] = e3*inv;
    }
    __syncthreads();
    float sum = 0.f;
#pragma unroll
    for (int h = 0; h < 4; h++)
        sum += s_p[h][tx] * g_ret[(size_t)s_d[h][tx]*32 + c];
    out[c*L + l] = sum + x[c*L + l];
}

// ---------------- launcher ---------------------------------------------------
extern "C" void kernel_launch(void* const* d_in, const int* in_sizes, int n_in,
                              void* d_out, int out_size) {
    const float* x   = (const float*)d_in[0];
    const float* wm  = (const float*)d_in[1];
    const float* bm  = (const float*)d_in[2];
    const float* wa  = (const float*)d_in[3];
    const float* ba  = (const float*)d_in[4];
    const float* rot = (const float*)d_in[5];
    float* out = (float*)d_out;

    k_embed_hash<<<L/128, 128>>>(x, wm, bm, wa, ba, rot);
    k_hist<<<NTILES, 256>>>();
    k_scanA<<<64, 256>>>();
    k_scanB<<<1, NCODES>>>();
    k_scatter<<<NTILES, 256>>>();
    k_gather<<<TOT*8/256, 256>>>();
    k_attn<<<NHASH*NCHUNK, 160>>>();
    k_combine<<<L/32, dim3(32,32)>>>(x, out);
}

// round 3
// speedup vs baseline: 1.9826x; 1.0019x over previous
#include <cuda_runtime.h>

#define L 36864
#define HH 192
#define NHASH 4
#define TOT (NHASH*L)        // 147456
#define CHUNK_ 144
#define NCHUNK 256
#define NCODES 512
#define TILE 1024
#define NTILES 144           // TOT / TILE

typedef unsigned long long ull;

// ---------------- scratch ----------------------------------------------------
__device__ __align__(16) float g_xe[L*8];
__device__ __align__(16) float g_ye[L*32];
__device__ int   g_code[TOT];
__device__ int   g_tileHist[NCODES*NTILES];      // TRANSPOSED: [code][tile]
__device__ int   g_tileOff[NCODES*NTILES];
__device__ int   g_codeTot[NCODES];
__device__ int   g_codeStart[NCODES];
__device__ int   g_sortIdx[TOT];
__device__ int   g_undo[TOT];
__device__ __align__(16) float g_xq[TOT*8];
__device__ __align__(16) float g_xn[TOT*8];
__device__ __align__(16) float g_ys[TOT*32];
__device__ __align__(16) float g_ret[TOT*32];
__device__ float g_bs[TOT];

// ---------------- f32x2 helpers ----------------------------------------------
__device__ __forceinline__ ull ffma2(ull a, ull b, ull c) {
    ull d;
    asm("fma.rn.f32x2 %0, %1, %2, %3;" : "=l"(d) : "l"(a), "l"(b), "l"(c));
    return d;
}
__device__ __forceinline__ ull fmul2(ull a, ull b) {
    ull d;
    asm("mul.rn.f32x2 %0, %1, %2;" : "=l"(d) : "l"(a), "l"(b));
    return d;
}
__device__ __forceinline__ ull pack2(float lo, float hi) {
    ull d;
    asm("mov.b64 %0, {%1, %2};" : "=l"(d)
        : "r"(__float_as_uint(lo)), "r"(__float_as_uint(hi)));
    return d;
}
__device__ __forceinline__ void unpack2(ull v, float& lo, float& hi) {
    unsigned int a, b;
    asm("mov.b64 {%0, %1}, %2;" : "=r"(a), "=r"(b) : "l"(v));
    lo = __uint_as_float(a); hi = __uint_as_float(b);
}

// ---------------- K1: fused convs + LSH hashing ------------------------------
__global__ void k_embed_hash(const float* __restrict__ x,
                             const float* __restrict__ wm,
                             const float* __restrict__ bm,
                             const float* __restrict__ wa,
                             const float* __restrict__ ba,
                             const float* __restrict__ rot) {
    __shared__ float s_wm[2304];
    __shared__ float s_wa[1024];
    __shared__ __align__(16) float s_rot[2048];  // transposed: [(h*64+i)][f=8]
    __shared__ float s_bm[8];
    __shared__ float s_ba[32];
    int tid = threadIdx.x;
    for (int t = tid; t < 2304; t += 128) s_wm[t] = wm[t];
    for (int t = tid; t < 1024; t += 128) s_wa[t] = wa[t];
    for (int t = tid; t < 2048; t += 128) {
        int f = t >> 8; int rem = t & 255;
        s_rot[rem*8 + f] = rot[t];
    }
    if (tid < 8)  s_bm[tid] = bm[tid];
    if (tid < 32) s_ba[tid] = ba[tid];
    __syncthreads();

    int pix = blockIdx.x*128 + tid;
    int py = pix / HH, px = pix - py*HH;
    float am[8], aa[32];
#pragma unroll
    for (int c = 0; c < 8;  c++) am[c] = s_bm[c];
#pragma unroll
    for (int c = 0; c < 32; c++) aa[c] = s_ba[c];

    bool yl = py > 0, yh = py < HH-1, xl = px > 0, xh = px < HH-1;
    for (int ci = 0; ci < 32; ci++) {
        const float* xc = x + ci*L + py*HH + px;
        float v[9];
        v[4] = xc[0];
        v[0] = (yl&&xl) ? xc[-HH-1] : 0.f;
        v[1] = yl        ? xc[-HH]   : 0.f;
        v[2] = (yl&&xh) ? xc[-HH+1] : 0.f;
        v[3] = xl        ? xc[-1]    : 0.f;
        v[5] = xh        ? xc[1]     : 0.f;
        v[6] = (yh&&xl) ? xc[HH-1]  : 0.f;
        v[7] = yh        ? xc[HH]    : 0.f;
        v[8] = (yh&&xh) ? xc[HH+1]  : 0.f;
#pragma unroll
        for (int co = 0; co < 8; co++) {
            const float* w = &s_wm[(co*32+ci)*9];
#pragma unroll
            for (int t = 0; t < 9; t++) am[co] += w[t]*v[t];
        }
        float vc = v[4];
#pragma unroll
        for (int co = 0; co < 32; co++) aa[co] += s_wa[co*32+ci]*vc;
    }
#pragma unroll
    for (int c = 0; c < 8;  c++) g_xe[pix*8+c]  = am[c];
#pragma unroll
    for (int c = 0; c < 32; c++) g_ye[pix*32+c] = aa[c];

    const float4* r4 = (const float4*)s_rot;
    float4 e0 = make_float4(am[0],am[1],am[2],am[3]);
    float4 e1 = make_float4(am[4],am[5],am[6],am[7]);
    for (int h = 0; h < NHASH; h++) {
        float bP = -1e30f, bN = -1e30f; int iP = 0, iN = 0;
        for (int i = 0; i < 64; i++) {
            float4 a = r4[(h*64+i)*2];
            float4 b = r4[(h*64+i)*2+1];
            float r = e0.x*a.x + e0.y*a.y + e0.z*a.z + e0.w*a.w
                    + e1.x*b.x + e1.y*b.y + e1.z*b.z + e1.w*b.w;
            if ( r > bP) { bP =  r; iP = i; }
            if (-r > bN) { bN = -r; iN = i; }
        }
        int code = (bN > bP) ? (64 + iN) : iP;
        g_code[h*L + pix] = code + h*128;
    }
}

// ---------------- stable counting sort (512 bins) ----------------------------
__global__ void k_hist() {
    __shared__ int hsh[NCODES];
    int tile = blockIdx.x;
    for (int c = threadIdx.x; c < NCODES; c += 256) hsh[c] = 0;
    __syncthreads();
    for (int t = threadIdx.x; t < TILE; t += 256)
        atomicAdd(&hsh[g_code[tile*TILE + t]], 1);
    __syncthreads();
    for (int c = threadIdx.x; c < NCODES; c += 256)
        g_tileHist[c*NTILES + tile] = hsh[c];
}

__global__ void k_scanA() {                            // one warp per code
    int c = blockIdx.x*8 + (threadIdx.x >> 5);
    int lane = threadIdx.x & 31;
    int run = 0;
    for (int base = 0; base < NTILES; base += 32) {
        int t = base + lane;
        int v = (t < NTILES) ? g_tileHist[c*NTILES + t] : 0;
        int incl = v;
#pragma unroll
        for (int o = 1; o < 32; o <<= 1) {
            int u = __shfl_up_sync(0xffffffffu, incl, o);
            if (lane >= o) incl += u;
        }
        if (t < NTILES) g_tileOff[c*NTILES + t] = run + incl - v;
        run += __shfl_sync(0xffffffffu, incl, 31);
    }
    if (lane == 0) g_codeTot[c] = run;
}

__global__ void k_scanB() {                            // 1 block, 512 threads
    __shared__ int s[NCODES];
    int c = threadIdx.x;
    s[c] = g_codeTot[c];
    __syncthreads();
    for (int off = 1; off < NCODES; off <<= 1) {
        int v = s[c];
        int add = (c >= off) ? s[c - off] : 0;
        __syncthreads();
        s[c] = v + add;
        __syncthreads();
    }
    g_codeStart[c] = (c == 0) ? 0 : s[c-1];
}

__global__ void k_scatter() {                          // 8 warps per tile, stable
    __shared__ int wcnt[8*NCODES];
    int tile = blockIdx.x;
    int tid = threadIdx.x, w = tid >> 5, lane = tid & 31;
    for (int c = tid; c < 8*NCODES; c += 256) wcnt[c] = 0;
    __syncthreads();
    int codes[4];
#pragma unroll
    for (int r = 0; r < 4; r++) {
        int p = tile*TILE + w*128 + r*32 + lane;
        int c = codes[r] = g_code[p];
        unsigned mask = __match_any_sync(0xffffffffu, c);
        int leader = __ffs(mask) - 1;
        if (lane == leader) wcnt[w*NCODES + c] += __popc(mask);
        __syncwarp();
    }
    __syncthreads();
    for (int c = tid; c < NCODES; c += 256) {
        int run = g_codeStart[c] + g_tileOff[c*NTILES + tile];
#pragma unroll
        for (int ww = 0; ww < 8; ww++) {
            int v = wcnt[ww*NCODES + c];
            wcnt[ww*NCODES + c] = run;
            run += v;
        }
    }
    __syncthreads();
#pragma unroll
    for (int r = 0; r < 4; r++) {
        int p = tile*TILE + w*128 + r*32 + lane;
        int c = codes[r];
        unsigned mask = __match_any_sync(0xffffffffu, c);
        int leader = __ffs(mask) - 1;
        int below  = __popc(mask & ((1u << lane) - 1u));
        int base = 0;
        if (lane == leader) {
            base = wcnt[w*NCODES + c];
            wcnt[w*NCODES + c] = base + __popc(mask);
        }
        base = __shfl_sync(0xffffffffu, base, leader);
        int dest = base + below;
        g_sortIdx[dest] = p;
        g_undo[p] = dest;
        __syncwarp();
    }
}

// ---------------- gather: 8 threads per sorted row ---------------------------
__global__ void k_gather() {
    int gt = blockIdx.x*256 + threadIdx.x;
    int s = gt >> 3, q = gt & 7;
    int p = g_sortIdx[s];
    int l = p % L;
    float v = g_xe[l*8 + q];
    float sq = v*v;
    sq += __shfl_xor_sync(0xffffffffu, sq, 1);
    sq += __shfl_xor_sync(0xffffffffu, sq, 2);
    sq += __shfl_xor_sync(0xffffffffu, sq, 4);
    float inv = 1.f / fmaxf(sqrtf(sq), 5e-5f);
    g_xq[s*8 + q] = v;
    g_xn[s*8 + q] = v*inv;
    ((float4*)g_ys)[s*8 + q] = ((const float4*)g_ye)[l*8 + q];
}

// ---------------- chunked attention: fixed-max single-pass + f32x2 -----------
// Keys are unit-norm (||k|| <= 1), so every score s = q.k satisfies s <= ||q||.
// Use m = ||q|| as the softmax max: exp(s-m) in (0,1], self-term == 1 so
// lsum >= 1. Single pass, no rescaling, minimal registers.
__global__ __launch_bounds__(160) void k_attn() {
    __shared__ __align__(16) ull s_kp[216*8];   // packed key pairs (13824 B)
    __shared__ __align__(16) ull s_y[48*16];    // 48-row value tile (6144 B)
    int blk = blockIdx.x;
    int h = blk >> 8, k = blk & 255;
    int tid = threadIdx.x;
    int hb = h*L;
    int kb1 = (k + 255) & 255, kb2 = (k + 1) & 255;
    int baseQ = hb + k*CHUNK_;
    int sb0 = hb + k*CHUNK_, sb1 = hb + kb1*CHUNK_, sb2 = hb + kb2*CHUNK_;

    // pack key pairs straight from global (L2-resident):
    // s_kp[jp*8+d] = (k[2jp][d], k[2jp+1][d])
    for (int e = tid; e < 1728; e += 160) {
        int jp = e >> 3, d = e & 7;
        int j0 = 2*jp;
        int seg = j0 / CHUNK_; int r0 = j0 - seg*CHUNK_;
        int sb = (seg == 0) ? sb0 : ((seg == 1) ? sb1 : sb2);
        const float* kr = g_xn + (size_t)(sb + r0)*8;
        s_kp[e] = pack2(kr[d], kr[8 + d]);
    }

    int i = tid;
    ull qq[8];
    ull acc[16];
    float m = 0.f, lsum = 0.f;
    if (i < CHUNK_) {
        const float* qp = g_xq + (size_t)(baseQ + i)*8;
        float nrm2 = 0.f;
#pragma unroll
        for (int d = 0; d < 8; d++) {
            float qv = qp[d];
            nrm2 += qv*qv;
            qq[d] = pack2(qv, qv);
        }
        m = sqrtf(nrm2);
#pragma unroll
        for (int q = 0; q < 16; q++) acc[q] = 0ull;
    }
    const ull* ys2 = (const ull*)g_ys;

    // 9 tiles of 48 keys; tiles are segment-aligned (144 = 3*48)
    for (int t = 0; t < 9; t++) {
        int seg = t / 3; int rr0 = (t - seg*3)*48;
        int sb = (seg == 0) ? sb0 : ((seg == 1) ? sb1 : sb2);
        __syncthreads();
        for (int e = tid; e < 768; e += 160) {
            int jr = e >> 4, qd = e & 15;
            s_y[e] = ys2[(size_t)(sb + rr0 + jr)*16 + qd];
        }
        __syncthreads();
        if (i < CHUNK_) {
#pragma unroll 6
            for (int jp = 0; jp < 24; jp++) {
                const ull* kp = &s_kp[(t*24 + jp)*8];
                ull sp = 0ull;
#pragma unroll
                for (int d = 0; d < 8; d++) sp = ffma2(qq[d], kp[d], sp);
                float lo, hi; unpack2(sp, lo, hi);
                float p0 = __expf(lo - m);
                float p1 = __expf(hi - m);
                lsum += p0 + p1;
                ull pp0 = pack2(p0, p0);
                ull pp1 = pack2(p1, p1);
                const ull* y0 = &s_y[(2*jp)*16];
                const ull* y1 = &s_y[(2*jp+1)*16];
#pragma unroll
                for (int q = 0; q < 16; q++) {
                    acc[q] = ffma2(pp0, y0[q], acc[q]);
                    acc[q] = ffma2(pp1, y1[q], acc[q]);
                }
            }
        }
    }
    if (i < CHUNK_) {
        float inv = 1.f / lsum;
        ull inv2 = pack2(inv, inv);
        int row = baseQ + i;
        ull* o = ((ull*)g_ret) + (size_t)row*16;
#pragma unroll
        for (int q = 0; q < 16; q++) o[q] = fmul2(acc[q], inv2);
        g_bs[row] = m + __logf(lsum);
    }
}

// ---------------- un-sort + cross-hash softmax + residual --------------------
__global__ void k_combine(const float* __restrict__ x, float* __restrict__ out) {
    __shared__ int   s_d[4][32];
    __shared__ float s_p[4][32];
    int tx = threadIdx.x, c = threadIdx.y;
    int l = blockIdx.x*32 + tx;
    if (c < 4) {
        int d = g_undo[c*L + l];
        s_d[c][tx] = d;
        s_p[c][tx] = g_bs[d];
    }
    __syncthreads();
    if (c == 0) {
        float b0 = s_p[0][tx], b1 = s_p[1][tx], b2 = s_p[2][tx], b3 = s_p[3][tx];
        float mm = fmaxf(fmaxf(b0,b1), fmaxf(b2,b3));
        float e0 = __expf(b0-mm), e1 = __expf(b1-mm), e2 = __expf(b2-mm), e3 = __expf(b3-mm);
        float inv = 1.f/(e0+e1+e2+e3);
        s_p[0][tx] = e0*inv; s_p[1][tx] = e1*inv; s_p[2][tx] = e2*inv; s_p[3][tx] = e3*inv;
    }
    __syncthreads();
    float sum = 0.f;
#pragma unroll
    for (int h = 0; h < 4; h++)
        sum += s_p[h][tx] * g_ret[(size_t)s_d[h][tx]*32 + c];
    out[c*L + l] = sum + x[c*L + l];
}

// ---------------- launcher ---------------------------------------------------
extern "C" void kernel_launch(void* const* d_in, const int* in_sizes, int n_in,
                              void* d_out, int out_size) {
    const float* x   = (const float*)d_in[0];
    const float* wm  = (const float*)d_in[1];
    const float* bm  = (const float*)d_in[2];
    const float* wa  = (const float*)d_in[3];
    const float* ba  = (const float*)d_in[4];
    const float* rot = (const float*)d_in[5];
    float* out = (float*)d_out;

    k_embed_hash<<<L/128, 128>>>(x, wm, bm, wa, ba, rot);
    k_hist<<<NTILES, 256>>>();
    k_scanA<<<64, 256>>>();
    k_scanB<<<1, NCODES>>>();
    k_scatter<<<NTILES, 256>>>();
    k_gather<<<TOT*8/256, 256>>>();
    k_attn<<<NHASH*NCHUNK, 160>>>();
    k_combine<<<L/32, dim3(32,32)>>>(x, out);
}